// round 15
// baseline (speedup 1.0000x reference)
#include <cuda_runtime.h>
#include <cuda_bf16.h>

#define S 8192
#define DM 64
#define HD 16
#define QT 128
#define CK 256
#define NCH (S / CK)           // 32
#define SCALE_LOG2E 0.3606737602222409f   // 0.25 * log2(e), folded into Q

typedef unsigned long long u64;
typedef unsigned int u32;
typedef unsigned short u16;

// ---- scratch (device globals; no allocation allowed) ----
// Q/K packed bf16x2 words [row][8] (word w = dims 2w,2w+1, even dim in LOW half).
__device__ u32 g_Qh[S * 8];
__device__ u32 g_Ql[S * 8];
__device__ u32 g_Kh[S * 8];
__device__ u32 g_Kl[S * 8];
__device__ u16 g_Vth[HD * S];  // V^T bf16 hi: [d][row]
__device__ u16 g_Vtl[HD * S];  // V^T bf16 lo residual
__device__ float g_l[NCH][S];
__device__ float g_O[NCH][S][HD];

// ======================= helpers =======================
__device__ __forceinline__ u64 fma2(u64 a, u64 b, u64 c) {
    u64 d; asm("fma.rn.f32x2 %0, %1, %2, %3;" : "=l"(d) : "l"(a), "l"(b), "l"(c)); return d;
}
__device__ __forceinline__ float hsum2(u64 a) {
    float x, y; asm("mov.b64 {%0, %1}, %2;" : "=f"(x), "=f"(y) : "l"(a)); return x + y;
}
__device__ __forceinline__ float ex2f(float s) {
    float p; asm("ex2.approx.f32 %0, %1;" : "=f"(p) : "f"(s)); return p;
}
__device__ __forceinline__ u32 bf16x2_rn(float lo, float hi) {   // LOW half = first arg
    u32 r; asm("cvt.rn.bf16x2.f32 %0, %1, %2;" : "=r"(r) : "f"(hi), "f"(lo)); return r;
}
__device__ __forceinline__ u16 bf16_rn(float a) {
    u16 r; asm("cvt.rn.bf16.f32 %0, %1;" : "=h"(r) : "f"(a)); return r;
}

// m16n8k16 bf16 MMA, D==C in-place accumulate
__device__ __forceinline__ void mma16816(float* c, u32 a0, u32 a1, u32 a2, u32 a3,
                                         u32 b0, u32 b1) {
    asm volatile(
        "mma.sync.aligned.m16n8k16.row.col.f32.bf16.bf16.f32 "
        "{%0,%1,%2,%3}, {%4,%5,%6,%7}, {%8,%9}, {%0,%1,%2,%3};"
        : "+f"(c[0]), "+f"(c[1]), "+f"(c[2]), "+f"(c[3])
        : "r"(a0), "r"(a1), "r"(a2), "r"(a3), "r"(b0), "r"(b1));
}

// ======================= projection (outer-product, W in regs) =======================
// grid = 128 blocks x 256 threads; block handles 64 rows (all blocks resident).
// Thread: col = (warp&1)*32 + lane in [0,64), active if col<48: m = col/16, d = col%16.
//         g = warp>>1 selects 16-row group.
// W row (64 floats) lives in 32 u64 registers; x read as LDS.64 BROADCASTS
// (all lanes same address). Q/K outputs transposed through smem; V^T direct.
__global__ __launch_bounds__(256) void proj_kernel(
    const float* __restrict__ x,
    const float* __restrict__ Wq, const float* __restrict__ bq,
    const float* __restrict__ Wk, const float* __restrict__ bk,
    const float* __restrict__ Wv, const float* __restrict__ bv) {
    __shared__ float sx[64][68];            // 17.4 KB, rows float4-aligned
    __shared__ u16 s_t[4][64][16];          // 8 KB: qh, ql, kh, kl (transposed staging)

    int t = threadIdx.x;
    int r0 = blockIdx.x * 64;

    // ---- stage x: 1024 float4, issued first (full-block MLP on DRAM) ----
#pragma unroll
    for (int i = 0; i < 4; i++) {
        int idx = t + i * 256;
        int row = idx >> 4, seg = idx & 15;
        float4 v = ((const float4*)(x + (r0 + row) * DM))[seg];
        *(float4*)&sx[row][seg * 4] = v;
    }

    int col  = ((t >> 5) & 1) * 32 + (t & 31);
    int g    = t >> 6;                       // row group 0..3
    bool act = col < 48;
    int m    = act ? (col >> 4) : 2;
    int d    = col & 15;

    const float* Wp = (m == 0) ? Wq : (m == 1) ? Wk : Wv;
    const float* bp = (m == 0) ? bq : (m == 1) ? bk : bv;

    u64 w2[32];
#pragma unroll
    for (int c2 = 0; c2 < 32; c2++) w2[c2] = *(const u64*)(Wp + d * DM + 2 * c2);
    float bias = bp[d];

    __syncthreads();

    // ---- 16 rows per thread: dual-chain fma2 dot, x broadcast from smem ----
    float o[16];
#pragma unroll
    for (int r = 0; r < 16; r++) {
        const float* xr = sx[g * 16 + r];
        u64 aa = 0ull, bb = 0ull;
#pragma unroll
        for (int c2 = 0; c2 < 32; c2 += 2) {
            aa = fma2(*(const u64*)(xr + 2 * c2),     w2[c2],     aa);
            bb = fma2(*(const u64*)(xr + 2 * c2 + 2), w2[c2 + 1], bb);
        }
        float s = hsum2(aa) + hsum2(bb) + bias;
        if (m == 0) s *= SCALE_LOG2E;
        o[r] = s;
    }

    // ---- emit ----
    if (act && m == 2) {
        // V^T: d row, 16 consecutive r -> pack pairs, 8 u32 stores each
        u32 hw[8], lw[8];
#pragma unroll
        for (int p = 0; p < 8; p++) {
            u16 h0 = bf16_rn(o[2 * p]);
            u16 h1 = bf16_rn(o[2 * p + 1]);
            float f0 = __uint_as_float((u32)h0 << 16);
            float f1 = __uint_as_float((u32)h1 << 16);
            u16 l0 = bf16_rn(o[2 * p] - f0);
            u16 l1 = bf16_rn(o[2 * p + 1] - f1);
            hw[p] = (u32)h0 | ((u32)h1 << 16);
            lw[p] = (u32)l0 | ((u32)l1 << 16);
        }
        int base = d * S + r0 + g * 16;
#pragma unroll
        for (int p = 0; p < 8; p++) {
            *(u32*)(g_Vth + base + 2 * p) = hw[p];
            *(u32*)(g_Vtl + base + 2 * p) = lw[p];
        }
    } else if (act) {
        // Q/K: stage transposed (hi and lo) in smem
        int ah = (m == 0) ? 0 : 2;
#pragma unroll
        for (int r = 0; r < 16; r++) {
            u16 h = bf16_rn(o[r]);
            float hf = __uint_as_float((u32)h << 16);
            s_t[ah][g * 16 + r][d]     = h;
            s_t[ah + 1][g * 16 + r][d] = bf16_rn(o[r] - hf);
        }
    }
    __syncthreads();

    // ---- coalesced Q/K writes: 4 arrays x 64 rows x 8 words ----
#pragma unroll
    for (int i = t; i < 2048; i += 256) {
        int a = i >> 9, row = (i >> 3) & 63, wd = i & 7;
        u32 v = *(const u32*)&s_t[a][row][2 * wd];
        u32* dst = (a == 0) ? g_Qh : (a == 1) ? g_Ql : (a == 2) ? g_Kh : g_Kl;
        dst[(r0 + row) * 8 + wd] = v;
    }
}

// ======================= attention (HMMA flash, split-K) =======================
// Grid (qt=64, ck=32), active iff qt >= 2*ck. 256 threads, 8 warps;
// warp w owns queries qr0+w*16..+15 vs keys k0..k0+255 (16 j-steps of 16 keys).
// Diagonal: qt==2ck -> j in [0,8) masked, j>=8 skipped; qt==2ck+1 -> j in [8,16) masked.
__global__ __launch_bounds__(256) void attn_kernel() {
    int qt = blockIdx.x, ck = blockIdx.y;
    if (qt < 2 * ck) return;
    int qr0 = qt * QT;
    int k0  = ck * CK;
    int tid = threadIdx.x;

    __shared__ __align__(16) u32 sK[256 * 24];       // 24 KB
    __shared__ __align__(16) u32 sVh[16 * 136];      // 8.5 KB
    __shared__ __align__(16) u32 sVl[16 * 136];      // 8.5 KB

#pragma unroll
    for (int i = tid; i < 2048; i += 256) {
        int key = i >> 3, w = i & 7;
        int iw = (w < 4) ? 2 * w : 2 * (w - 4) + 1;
        sK[key * 24 + iw]     = g_Kh[(k0 + key) * 8 + w];
        sK[key * 24 + 8 + iw] = g_Kl[(k0 + key) * 8 + w];
    }
#pragma unroll
    for (int i = tid; i < 2048; i += 256) {
        int d = i >> 7, c = i & 127;
        int grp = c >> 3, cc = c & 7;
        int widx = (cc < 4) ? 2 * cc : 2 * (cc - 4) + 1;
        sVh[d * 136 + grp * 8 + widx] = *(const u32*)(g_Vth + d * S + k0 + 2 * c);
        sVl[d * 136 + grp * 8 + widx] = *(const u32*)(g_Vtl + d * S + k0 + 2 * c);
    }
    __syncthreads();

    int w    = tid >> 5;
    int lane = tid & 31;
    int grp  = lane >> 2;
    int tig  = lane & 3;
    int rl   = qr0 + w * 16 + grp;

    u32 qh[4], ql[4];
    qh[0] = g_Qh[rl * 8 + tig];           qh[1] = g_Qh[(rl + 8) * 8 + tig];
    qh[2] = g_Qh[rl * 8 + 4 + tig];       qh[3] = g_Qh[(rl + 8) * 8 + 4 + tig];
    ql[0] = g_Ql[rl * 8 + tig];           ql[1] = g_Ql[(rl + 8) * 8 + tig];
    ql[2] = g_Ql[rl * 8 + 4 + tig];       ql[3] = g_Ql[(rl + 8) * 8 + 4 + tig];

    float o0[4] = {0.f, 0.f, 0.f, 0.f};
    float o1[4] = {0.f, 0.f, 0.f, 0.f};
    float lsl = 0.f, lsh = 0.f;

    bool du = (qt == 2 * ck);
    bool dv = (qt == 2 * ck + 1);
    int jend = du ? 8 : 16;

#pragma unroll 4
    for (int j = 0; j < jend; j++) {
        float s0[4] = {0.f, 0.f, 0.f, 0.f};
        float s1[4] = {0.f, 0.f, 0.f, 0.f};
        {
            int kb = (2 * j) * 8 + grp;
            u64 kh = *(const u64*)(sK + kb * 24 + 2 * tig);
            u64 kl = *(const u64*)(sK + kb * 24 + 8 + 2 * tig);
            u32 khb0 = (u32)kh, khb1 = (u32)(kh >> 32);
            u32 klb0 = (u32)kl, klb1 = (u32)(kl >> 32);
            mma16816(s0, qh[0], qh[1], qh[2], qh[3], khb0, khb1);
            mma16816(s0, ql[0], ql[1], ql[2], ql[3], khb0, khb1);
            mma16816(s0, qh[0], qh[1], qh[2], qh[3], klb0, klb1);
        }
        {
            int kb = (2 * j + 1) * 8 + grp;
            u64 kh = *(const u64*)(sK + kb * 24 + 2 * tig);
            u64 kl = *(const u64*)(sK + kb * 24 + 8 + 2 * tig);
            u32 khb0 = (u32)kh, khb1 = (u32)(kh >> 32);
            u32 klb0 = (u32)kl, klb1 = (u32)(kl >> 32);
            mma16816(s1, qh[0], qh[1], qh[2], qh[3], khb0, khb1);
            mma16816(s1, ql[0], ql[1], ql[2], ql[3], khb0, khb1);
            mma16816(s1, qh[0], qh[1], qh[2], qh[3], klb0, klb1);
        }
        float p00 = ex2f(s0[0]), p01 = ex2f(s0[1]), p02 = ex2f(s0[2]), p03 = ex2f(s0[3]);
        float p10 = ex2f(s1[0]), p11 = ex2f(s1[1]), p12 = ex2f(s1[2]), p13 = ex2f(s1[3]);
        if (du || (dv && j >= 8)) {
            int c0 = k0 + 16 * j + 2 * tig;
            int c1 = c0 + 8;
            int rh = rl + 8;
            if (c0     > rl) p00 = 0.f;
            if (c0 + 1 > rl) p01 = 0.f;
            if (c0     > rh) p02 = 0.f;
            if (c0 + 1 > rh) p03 = 0.f;
            if (c1     > rl) p10 = 0.f;
            if (c1 + 1 > rl) p11 = 0.f;
            if (c1     > rh) p12 = 0.f;
            if (c1 + 1 > rh) p13 = 0.f;
        }
        lsl += p00 + p01 + p10 + p11;
        lsh += p02 + p03 + p12 + p13;

        u32 pah[4], pal[4];
        {
            u32 h;
            h = bf16x2_rn(p00, p01); pah[0] = h;
            pal[0] = bf16x2_rn(p00 - __uint_as_float(h << 16),
                               p01 - __uint_as_float(h & 0xffff0000u));
            h = bf16x2_rn(p02, p03); pah[1] = h;
            pal[1] = bf16x2_rn(p02 - __uint_as_float(h << 16),
                               p03 - __uint_as_float(h & 0xffff0000u));
            h = bf16x2_rn(p10, p11); pah[2] = h;
            pal[2] = bf16x2_rn(p10 - __uint_as_float(h << 16),
                               p11 - __uint_as_float(h & 0xffff0000u));
            h = bf16x2_rn(p12, p13); pah[3] = h;
            pal[3] = bf16x2_rn(p12 - __uint_as_float(h << 16),
                               p13 - __uint_as_float(h & 0xffff0000u));
        }
        {
            u64 vh = *(const u64*)(sVh + grp * 136 + j * 8 + 2 * tig);
            u64 vl = *(const u64*)(sVl + grp * 136 + j * 8 + 2 * tig);
            u32 vhb0 = (u32)vh, vhb1 = (u32)(vh >> 32);
            u32 vlb0 = (u32)vl, vlb1 = (u32)(vl >> 32);
            mma16816(o0, pah[0], pah[1], pah[2], pah[3], vhb0, vhb1);
            mma16816(o0, pal[0], pal[1], pal[2], pal[3], vhb0, vhb1);
            mma16816(o0, pah[0], pah[1], pah[2], pah[3], vlb0, vlb1);
        }
        {
            u64 vh = *(const u64*)(sVh + (grp + 8) * 136 + j * 8 + 2 * tig);
            u64 vl = *(const u64*)(sVl + (grp + 8) * 136 + j * 8 + 2 * tig);
            u32 vhb0 = (u32)vh, vhb1 = (u32)(vh >> 32);
            u32 vlb0 = (u32)vl, vlb1 = (u32)(vl >> 32);
            mma16816(o1, pah[0], pah[1], pah[2], pah[3], vhb0, vhb1);
            mma16816(o1, pal[0], pal[1], pal[2], pal[3], vhb0, vhb1);
            mma16816(o1, pah[0], pah[1], pah[2], pah[3], vlb0, vlb1);
        }
    }

    lsl += __shfl_xor_sync(0xffffffffu, lsl, 1);
    lsl += __shfl_xor_sync(0xffffffffu, lsl, 2);
    lsh += __shfl_xor_sync(0xffffffffu, lsh, 1);
    lsh += __shfl_xor_sync(0xffffffffu, lsh, 2);
    if (tig == 0) {
        g_l[ck][rl]     = lsl;
        g_l[ck][rl + 8] = lsh;
    }

    *(float2*)&g_O[ck][rl][2 * tig]         = make_float2(o0[0], o0[1]);
    *(float2*)&g_O[ck][rl + 8][2 * tig]     = make_float2(o0[2], o0[3]);
    *(float2*)&g_O[ck][rl][8 + 2 * tig]     = make_float2(o1[0], o1[1]);
    *(float2*)&g_O[ck][rl + 8][8 + 2 * tig] = make_float2(o1[2], o1[3]);
}

// ======================= reduce (4-way unrolled for MLP) =======================
__global__ __launch_bounds__(256) void reduce_kernel(float* __restrict__ out) {
    int idx = blockIdx.x * 256 + threadIdx.x;
    int r  = idx >> 2;
    int d4 = idx & 3;
    int nc = r / CK + 1;

    float L0 = 0.f, L1 = 0.f, L2 = 0.f, L3 = 0.f;
    float4 a0 = make_float4(0.f, 0.f, 0.f, 0.f);
    float4 a1 = make_float4(0.f, 0.f, 0.f, 0.f);
    float4 a2 = make_float4(0.f, 0.f, 0.f, 0.f);
    float4 a3 = make_float4(0.f, 0.f, 0.f, 0.f);

    int c = 0;
    for (; c + 4 <= nc; c += 4) {
        float4 p0 = ((const float4*)g_O[c][r])[d4];
        float4 p1 = ((const float4*)g_O[c + 1][r])[d4];
        float4 p2 = ((const float4*)g_O[c + 2][r])[d4];
        float4 p3 = ((const float4*)g_O[c + 3][r])[d4];
        L0 += g_l[c][r];     L1 += g_l[c + 1][r];
        L2 += g_l[c + 2][r]; L3 += g_l[c + 3][r];
        a0.x += p0.x; a0.y += p0.y; a0.z += p0.z; a0.w += p0.w;
        a1.x += p1.x; a1.y += p1.y; a1.z += p1.z; a1.w += p1.w;
        a2.x += p2.x; a2.y += p2.y; a2.z += p2.z; a2.w += p2.w;
        a3.x += p3.x; a3.y += p3.y; a3.z += p3.z; a3.w += p3.w;
    }
    for (; c < nc; c++) {
        float4 p = ((const float4*)g_O[c][r])[d4];
        L0 += g_l[c][r];
        a0.x += p.x; a0.y += p.y; a0.z += p.z; a0.w += p.w;
    }
    float L = (L0 + L1) + (L2 + L3);
    float4 o = make_float4((a0.x + a1.x) + (a2.x + a3.x),
                           (a0.y + a1.y) + (a2.y + a3.y),
                           (a0.z + a1.z) + (a2.z + a3.z),
                           (a0.w + a1.w) + (a2.w + a3.w));
    float inv = 1.f / L;
    ((float4*)(out + r * HD))[d4] =
        make_float4(o.x * inv, o.y * inv, o.z * inv, o.w * inv);
}

extern "C" void kernel_launch(void* const* d_in, const int* in_sizes, int n_in,
                              void* d_out, int out_size) {
    const float* x  = (const float*)d_in[0];
    const float* Wq = (const float*)d_in[1];
    const float* bq = (const float*)d_in[2];
    const float* Wk = (const float*)d_in[3];
    const float* bk = (const float*)d_in[4];
    const float* Wv = (const float*)d_in[5];
    const float* bv = (const float*)d_in[6];
    float* out = (float*)d_out;

    proj_kernel<<<S / 64, 256>>>(x, Wq, bq, Wk, bk, Wv, bv);
    attn_kernel<<<dim3(S / QT, NCH), 256>>>();
    reduce_kernel<<<S * 4 / 256, 256>>>(out);
}

// round 17
// speedup vs baseline: 1.0603x; 1.0603x over previous
#include <cuda_runtime.h>
#include <cuda_bf16.h>

#define S 8192
#define DM 64
#define HD 16
#define QT 128
#define CK 256
#define NCH (S / CK)           // 32
#define SCALE_LOG2E 0.3606737602222409f   // 0.25 * log2(e), folded into Wq/bq

typedef unsigned long long u64;
typedef unsigned int u32;
typedef unsigned short u16;

// ---- scratch (device globals; no allocation allowed) ----
// Q/K packed bf16x2 words [row][8] (word w = dims 2w,2w+1, even dim in LOW half).
__device__ u32 g_Qh[S * 8];
__device__ u32 g_Ql[S * 8];
__device__ u32 g_Kh[S * 8];
__device__ u32 g_Kl[S * 8];
__device__ u16 g_Vth[HD * S];  // V^T bf16 hi: [d][row]
__device__ u16 g_Vtl[HD * S];  // V^T bf16 lo residual
__device__ float g_l[NCH][S];
__device__ float g_O[NCH][S][HD];

// ======================= helpers =======================
__device__ __forceinline__ float ex2f(float s) {
    float p; asm("ex2.approx.f32 %0, %1;" : "=f"(p) : "f"(s)); return p;
}
__device__ __forceinline__ u32 bf16x2_rn(float lo, float hi) {   // LOW half = first arg
    u32 r; asm("cvt.rn.bf16x2.f32 %0, %1, %2;" : "=r"(r) : "f"(hi), "f"(lo)); return r;
}
__device__ __forceinline__ u16 bf16_rn(float a) {
    u16 r; asm("cvt.rn.bf16.f32 %0, %1;" : "=h"(r) : "f"(a)); return r;
}
// split pair (c0,c1) into hi word + lo-residual word
__device__ __forceinline__ void split2(float c0, float c1, u32& h, u32& l) {
    h = bf16x2_rn(c0, c1);
    l = bf16x2_rn(c0 - __uint_as_float(h << 16),
                  c1 - __uint_as_float(h & 0xffff0000u));
}

// m16n8k16 bf16 MMA, D==C in-place accumulate
__device__ __forceinline__ void mma16816(float* c, u32 a0, u32 a1, u32 a2, u32 a3,
                                         u32 b0, u32 b1) {
    asm volatile(
        "mma.sync.aligned.m16n8k16.row.col.f32.bf16.bf16.f32 "
        "{%0,%1,%2,%3}, {%4,%5,%6,%7}, {%8,%9}, {%0,%1,%2,%3};"
        : "+f"(c[0]), "+f"(c[1]), "+f"(c[2]), "+f"(c[3])
        : "r"(a0), "r"(a1), "r"(a2), "r"(a3), "r"(b0), "r"(b1));
}

// ======================= projection (HMMA GEMM) =======================
// x[8192,64] @ W^T[64,48] on the tensor pipe. grid = 128 blocks x 128 threads
// (4 warps); block handles 64 rows, warp w the 16-row tile w.
// Phase 1: convert x rows and all W to bf16 hi/lo in smem (read ONCE).
// Phase 2: per warp 6 n-tiles x 4 k-tiles x 3 MMAs (Ah*Bh + Al*Bh + Ah*Bl).
// Phase 3: C fragments map directly onto g_Qh/g_Kh words and V^T entries.
__global__ __launch_bounds__(128) void proj_kernel(
    const float* __restrict__ x,
    const float* __restrict__ Wq, const float* __restrict__ bq,
    const float* __restrict__ Wk, const float* __restrict__ bk,
    const float* __restrict__ Wv, const float* __restrict__ bv) {
    __shared__ u16 sXh[64][68], sXl[64][68];    // 17.4 KB
    __shared__ u16 sWh[48][68], sWl[48][68];    // 13.1 KB
    __shared__ float sbias[48];

    int t = threadIdx.x;
    int r0 = blockIdx.x * 64;

    // ---- phase 1a: x rows -> bf16 hi/lo (thread: row t>>1, half t&1) ----
    {
        int row = t >> 1, half = t & 1;
        const float4* xg = (const float4*)(x + (r0 + row) * DM + half * 32);
#pragma unroll
        for (int i = 0; i < 8; i++) {
            float4 v = xg[i];
            u32 h01, l01, h23, l23;
            split2(v.x, v.y, h01, l01);
            split2(v.z, v.w, h23, l23);
            int c = half * 32 + 4 * i;
            *(u32*)&sXh[row][c]     = h01;
            *(u32*)&sXh[row][c + 2] = h23;
            *(u32*)&sXl[row][c]     = l01;
            *(u32*)&sXl[row][c + 2] = l23;
        }
    }
    // ---- phase 1b: W -> bf16 hi/lo (Q rows pre-scaled) ----
    for (int i = t; i < 3072; i += 128) {
        int n = i >> 6, c = i & 63;
        const float* Wp = (n < 16) ? Wq : (n < 32) ? Wk : Wv;
        float v = Wp[(n & 15) * DM + c];
        if (n < 16) v *= SCALE_LOG2E;
        u16 h = bf16_rn(v);
        sWh[n][c] = h;
        sWl[n][c] = bf16_rn(v - __uint_as_float((u32)h << 16));
    }
    if (t < 48) {
        const float* bp = (t < 16) ? bq : (t < 32) ? bk : bv;
        float v = bp[t & 15];
        if (t < 16) v *= SCALE_LOG2E;
        sbias[t] = v;
    }
    __syncthreads();

    // ---- phase 2: MMAs ----
    int w    = t >> 5;
    int lane = t & 31;
    int grp  = lane >> 2;
    int tig  = lane & 3;
    int rloc = w * 16 + grp;

    u32 ah[4][4], al[4][4];
#pragma unroll
    for (int kt = 0; kt < 4; kt++) {
        int kk = kt * 16 + 2 * tig;
        ah[kt][0] = *(const u32*)&sXh[rloc][kk];
        ah[kt][1] = *(const u32*)&sXh[rloc + 8][kk];
        ah[kt][2] = *(const u32*)&sXh[rloc][kk + 8];
        ah[kt][3] = *(const u32*)&sXh[rloc + 8][kk + 8];
        al[kt][0] = *(const u32*)&sXl[rloc][kk];
        al[kt][1] = *(const u32*)&sXl[rloc + 8][kk];
        al[kt][2] = *(const u32*)&sXl[rloc][kk + 8];
        al[kt][3] = *(const u32*)&sXl[rloc + 8][kk + 8];
    }

    float acc[6][4];
#pragma unroll
    for (int nt = 0; nt < 6; nt++)
#pragma unroll
        for (int i = 0; i < 4; i++) acc[nt][i] = 0.f;

#pragma unroll
    for (int nt = 0; nt < 6; nt++) {
        int n = nt * 8 + grp;
#pragma unroll
        for (int kt = 0; kt < 4; kt++) {
            int kk = kt * 16 + 2 * tig;
            u32 bh0 = *(const u32*)&sWh[n][kk];
            u32 bh1 = *(const u32*)&sWh[n][kk + 8];
            u32 bl0 = *(const u32*)&sWl[n][kk];
            u32 bl1 = *(const u32*)&sWl[n][kk + 8];
            mma16816(acc[nt], ah[kt][0], ah[kt][1], ah[kt][2], ah[kt][3], bh0, bh1);
            mma16816(acc[nt], al[kt][0], al[kt][1], al[kt][2], al[kt][3], bh0, bh1);
            mma16816(acc[nt], ah[kt][0], ah[kt][1], ah[kt][2], ah[kt][3], bl0, bl1);
        }
    }

    // ---- phase 3: bias, split, store ----
    int gr = r0 + rloc;                  // low row; high row = gr + 8
#pragma unroll
    for (int nt = 0; nt < 6; nt++) {
        float b0 = sbias[nt * 8 + 2 * tig];
        float b1 = sbias[nt * 8 + 2 * tig + 1];
        float c0 = acc[nt][0] + b0, c1 = acc[nt][1] + b1;
        float c2 = acc[nt][2] + b0, c3 = acc[nt][3] + b1;
        u32 h01, l01, h23, l23;
        split2(c0, c1, h01, l01);
        split2(c2, c3, h23, l23);
        if (nt < 2) {
            int wd = nt * 4 + tig;
            g_Qh[gr * 8 + wd]       = h01;
            g_Ql[gr * 8 + wd]       = l01;
            g_Qh[(gr + 8) * 8 + wd] = h23;
            g_Ql[(gr + 8) * 8 + wd] = l23;
        } else if (nt < 4) {
            int wd = (nt - 2) * 4 + tig;
            g_Kh[gr * 8 + wd]       = h01;
            g_Kl[gr * 8 + wd]       = l01;
            g_Kh[(gr + 8) * 8 + wd] = h23;
            g_Kl[(gr + 8) * 8 + wd] = l23;
        } else {
            int d0 = (nt - 4) * 8 + 2 * tig;
            g_Vth[d0 * S + gr]           = (u16)(h01 & 0xffffu);
            g_Vth[(d0 + 1) * S + gr]     = (u16)(h01 >> 16);
            g_Vtl[d0 * S + gr]           = (u16)(l01 & 0xffffu);
            g_Vtl[(d0 + 1) * S + gr]     = (u16)(l01 >> 16);
            g_Vth[d0 * S + gr + 8]       = (u16)(h23 & 0xffffu);
            g_Vth[(d0 + 1) * S + gr + 8] = (u16)(h23 >> 16);
            g_Vtl[d0 * S + gr + 8]       = (u16)(l23 & 0xffffu);
            g_Vtl[(d0 + 1) * S + gr + 8] = (u16)(l23 >> 16);
        }
    }
}

// ======================= attention (HMMA flash, split-K) =======================
// Grid (qt=64, ck=32), active iff qt >= 2*ck. 256 threads, 8 warps;
// warp w owns queries qr0+w*16..+15 vs keys k0..k0+255 (16 j-steps of 16 keys).
// Diagonal: qt==2ck -> j in [0,8) masked, j>=8 skipped; qt==2ck+1 -> j in [8,16) masked.
__global__ __launch_bounds__(256) void attn_kernel() {
    int qt = blockIdx.x, ck = blockIdx.y;
    if (qt < 2 * ck) return;
    int qr0 = qt * QT;
    int k0  = ck * CK;
    int tid = threadIdx.x;

    __shared__ __align__(16) u32 sK[256 * 24];       // 24 KB
    __shared__ __align__(16) u32 sVh[16 * 136];      // 8.5 KB
    __shared__ __align__(16) u32 sVl[16 * 136];      // 8.5 KB

#pragma unroll
    for (int i = tid; i < 2048; i += 256) {
        int key = i >> 3, w = i & 7;
        int iw = (w < 4) ? 2 * w : 2 * (w - 4) + 1;
        sK[key * 24 + iw]     = g_Kh[(k0 + key) * 8 + w];
        sK[key * 24 + 8 + iw] = g_Kl[(k0 + key) * 8 + w];
    }
#pragma unroll
    for (int i = tid; i < 2048; i += 256) {
        int d = i >> 7, c = i & 127;
        int grp = c >> 3, cc = c & 7;
        int widx = (cc < 4) ? 2 * cc : 2 * (cc - 4) + 1;
        sVh[d * 136 + grp * 8 + widx] = *(const u32*)(g_Vth + d * S + k0 + 2 * c);
        sVl[d * 136 + grp * 8 + widx] = *(const u32*)(g_Vtl + d * S + k0 + 2 * c);
    }
    __syncthreads();

    int w    = tid >> 5;
    int lane = tid & 31;
    int grp  = lane >> 2;
    int tig  = lane & 3;
    int rl   = qr0 + w * 16 + grp;

    u32 qh[4], ql[4];
    qh[0] = g_Qh[rl * 8 + tig];           qh[1] = g_Qh[(rl + 8) * 8 + tig];
    qh[2] = g_Qh[rl * 8 + 4 + tig];       qh[3] = g_Qh[(rl + 8) * 8 + 4 + tig];
    ql[0] = g_Ql[rl * 8 + tig];           ql[1] = g_Ql[(rl + 8) * 8 + tig];
    ql[2] = g_Ql[rl * 8 + 4 + tig];       ql[3] = g_Ql[(rl + 8) * 8 + 4 + tig];

    float o0[4] = {0.f, 0.f, 0.f, 0.f};
    float o1[4] = {0.f, 0.f, 0.f, 0.f};
    float lsl = 0.f, lsh = 0.f;

    bool du = (qt == 2 * ck);
    bool dv = (qt == 2 * ck + 1);
    int jend = du ? 8 : 16;

#pragma unroll 4
    for (int j = 0; j < jend; j++) {
        float s0[4] = {0.f, 0.f, 0.f, 0.f};
        float s1[4] = {0.f, 0.f, 0.f, 0.f};
        {
            int kb = (2 * j) * 8 + grp;
            u64 kh = *(const u64*)(sK + kb * 24 + 2 * tig);
            u64 kl = *(const u64*)(sK + kb * 24 + 8 + 2 * tig);
            u32 khb0 = (u32)kh, khb1 = (u32)(kh >> 32);
            u32 klb0 = (u32)kl, klb1 = (u32)(kl >> 32);
            mma16816(s0, qh[0], qh[1], qh[2], qh[3], khb0, khb1);
            mma16816(s0, ql[0], ql[1], ql[2], ql[3], khb0, khb1);
            mma16816(s0, qh[0], qh[1], qh[2], qh[3], klb0, klb1);
        }
        {
            int kb = (2 * j + 1) * 8 + grp;
            u64 kh = *(const u64*)(sK + kb * 24 + 2 * tig);
            u64 kl = *(const u64*)(sK + kb * 24 + 8 + 2 * tig);
            u32 khb0 = (u32)kh, khb1 = (u32)(kh >> 32);
            u32 klb0 = (u32)kl, klb1 = (u32)(kl >> 32);
            mma16816(s1, qh[0], qh[1], qh[2], qh[3], khb0, khb1);
            mma16816(s1, ql[0], ql[1], ql[2], ql[3], khb0, khb1);
            mma16816(s1, qh[0], qh[1], qh[2], qh[3], klb0, klb1);
        }
        float p00 = ex2f(s0[0]), p01 = ex2f(s0[1]), p02 = ex2f(s0[2]), p03 = ex2f(s0[3]);
        float p10 = ex2f(s1[0]), p11 = ex2f(s1[1]), p12 = ex2f(s1[2]), p13 = ex2f(s1[3]);
        if (du || (dv && j >= 8)) {
            int c0 = k0 + 16 * j + 2 * tig;
            int c1 = c0 + 8;
            int rh = rl + 8;
            if (c0     > rl) p00 = 0.f;
            if (c0 + 1 > rl) p01 = 0.f;
            if (c0     > rh) p02 = 0.f;
            if (c0 + 1 > rh) p03 = 0.f;
            if (c1     > rl) p10 = 0.f;
            if (c1 + 1 > rl) p11 = 0.f;
            if (c1     > rh) p12 = 0.f;
            if (c1 + 1 > rh) p13 = 0.f;
        }
        lsl += p00 + p01 + p10 + p11;
        lsh += p02 + p03 + p12 + p13;

        u32 pah[4], pal[4];
        split2(p00, p01, pah[0], pal[0]);
        split2(p02, p03, pah[1], pal[1]);
        split2(p10, p11, pah[2], pal[2]);
        split2(p12, p13, pah[3], pal[3]);
        {
            u64 vh = *(const u64*)(sVh + grp * 136 + j * 8 + 2 * tig);
            u64 vl = *(const u64*)(sVl + grp * 136 + j * 8 + 2 * tig);
            u32 vhb0 = (u32)vh, vhb1 = (u32)(vh >> 32);
            u32 vlb0 = (u32)vl, vlb1 = (u32)(vl >> 32);
            mma16816(o0, pah[0], pah[1], pah[2], pah[3], vhb0, vhb1);
            mma16816(o0, pal[0], pal[1], pal[2], pal[3], vhb0, vhb1);
            mma16816(o0, pah[0], pah[1], pah[2], pah[3], vlb0, vlb1);
        }
        {
            u64 vh = *(const u64*)(sVh + (grp + 8) * 136 + j * 8 + 2 * tig);
            u64 vl = *(const u64*)(sVl + (grp + 8) * 136 + j * 8 + 2 * tig);
            u32 vhb0 = (u32)vh, vhb1 = (u32)(vh >> 32);
            u32 vlb0 = (u32)vl, vlb1 = (u32)(vl >> 32);
            mma16816(o1, pah[0], pah[1], pah[2], pah[3], vhb0, vhb1);
            mma16816(o1, pal[0], pal[1], pal[2], pal[3], vhb0, vhb1);
            mma16816(o1, pah[0], pah[1], pah[2], pah[3], vlb0, vlb1);
        }
    }

    lsl += __shfl_xor_sync(0xffffffffu, lsl, 1);
    lsl += __shfl_xor_sync(0xffffffffu, lsl, 2);
    lsh += __shfl_xor_sync(0xffffffffu, lsh, 1);
    lsh += __shfl_xor_sync(0xffffffffu, lsh, 2);
    if (tig == 0) {
        g_l[ck][rl]     = lsl;
        g_l[ck][rl + 8] = lsh;
    }

    *(float2*)&g_O[ck][rl][2 * tig]         = make_float2(o0[0], o0[1]);
    *(float2*)&g_O[ck][rl + 8][2 * tig]     = make_float2(o0[2], o0[3]);
    *(float2*)&g_O[ck][rl][8 + 2 * tig]     = make_float2(o1[0], o1[1]);
    *(float2*)&g_O[ck][rl + 8][8 + 2 * tig] = make_float2(o1[2], o1[3]);
}

// ======================= reduce (R14 simple form) =======================
__global__ __launch_bounds__(256) void reduce_kernel(float* __restrict__ out) {
    int idx = blockIdx.x * 256 + threadIdx.x;
    int r  = idx >> 2;
    int d4 = idx & 3;
    int nc = r / CK + 1;
    float L = 0.f;
    float4 o = make_float4(0.f, 0.f, 0.f, 0.f);
    for (int c = 0; c < nc; c++) {
        L += g_l[c][r];
        float4 p = ((const float4*)g_O[c][r])[d4];
        o.x += p.x; o.y += p.y; o.z += p.z; o.w += p.w;
    }
    float inv = 1.f / L;
    ((float4*)(out + r * HD))[d4] =
        make_float4(o.x * inv, o.y * inv, o.z * inv, o.w * inv);
}

extern "C" void kernel_launch(void* const* d_in, const int* in_sizes, int n_in,
                              void* d_out, int out_size) {
    const float* x  = (const float*)d_in[0];
    const float* Wq = (const float*)d_in[1];
    const float* bq = (const float*)d_in[2];
    const float* Wk = (const float*)d_in[3];
    const float* bk = (const float*)d_in[4];
    const float* Wv = (const float*)d_in[5];
    const float* bv = (const float*)d_in[6];
    float* out = (float*)d_out;

    proj_kernel<<<S / 64, 128>>>(x, Wq, bq, Wk, bk, Wv, bv);
    attn_kernel<<<dim3(S / QT, NCH), 256>>>();
    reduce_kernel<<<S * 4 / 256, 256>>>(out);
}